// round 14
// baseline (speedup 1.0000x reference)
#include <cuda_runtime.h>
#include <cuda_fp16.h>
#include <cstdint>

// Problem constants
#define BATCH 8
#define SEQ   4096
#define EMB   512
#define NHEAD 8
#define HDIM  64
#define BS_ROWS (BATCH*SEQ)          // 32768
#define NCHUNK 16

// Scratch (device globals: allocation-free contract)
__device__ __half g_xh [BS_ROWS * EMB];
__device__ __half g_qh [BS_ROWS * EMB];
__device__ __half g_kt [BS_ROWS * EMB];            // KT[bh][chunk][d][256]
__device__ __half g_vt [BS_ROWS * EMB];            // VT[bh][chunk][m][256]
__device__ __half g_oh [BS_ROWS * EMB];
__device__ __half g_wth[4 * EMB * EMB];            // transposed half weights [N][K]
__device__ float  g_kvp[NCHUNK * 64 * HDIM * HDIM];// [chunk][bh][d][m]
__device__ float  g_ksp[NCHUNK * 64 * HDIM];       // [chunk][bh][d]
__device__ __half g_kvh[64 * (HDIM * HDIM + HDIM)];// [bh][ m*64+d ; 4096+ksum ]

// ---------------------------------------------------------------------------
// PTX helpers
// ---------------------------------------------------------------------------
__device__ __forceinline__ void mma_h(float* d, const uint32_t* a, uint32_t b0, uint32_t b1) {
    asm volatile(
        "mma.sync.aligned.m16n8k16.row.col.f32.f16.f16.f32 "
        "{%0,%1,%2,%3}, {%4,%5,%6,%7}, {%8,%9}, {%0,%1,%2,%3};"
        : "+f"(d[0]), "+f"(d[1]), "+f"(d[2]), "+f"(d[3])
        : "r"(a[0]), "r"(a[1]), "r"(a[2]), "r"(a[3]), "r"(b0), "r"(b1));
}
__device__ __forceinline__ void ldm_x4(uint32_t* r, uint32_t addr) {
    asm volatile("ldmatrix.sync.aligned.m8n8.x4.shared.b16 {%0,%1,%2,%3}, [%4];"
        : "=r"(r[0]), "=r"(r[1]), "=r"(r[2]), "=r"(r[3]) : "r"(addr));
}
__device__ __forceinline__ void cp_async16(uint32_t smem_addr, const void* gptr) {
    asm volatile("cp.async.cg.shared.global [%0], [%1], 16;" :: "r"(smem_addr), "l"(gptr));
}
__device__ __forceinline__ void cp_commit() { asm volatile("cp.async.commit_group;"); }
template <int N>
__device__ __forceinline__ void cp_wait() { asm volatile("cp.async.wait_group %0;" :: "n"(N)); }

// ---------------------------------------------------------------------------
// x -> half conversion
// ---------------------------------------------------------------------------
__global__ __launch_bounds__(256)
void f2h_kernel(const float* __restrict__ X, __half* __restrict__ Xh, int n4) {
    int i = blockIdx.x * blockDim.x + threadIdx.x;
    if (i < n4) {
        float4 v = reinterpret_cast<const float4*>(X)[i];
        reinterpret_cast<__half2*>(Xh)[i * 2]     = __floats2half2_rn(v.x, v.y);
        reinterpret_cast<__half2*>(Xh)[i * 2 + 1] = __floats2half2_rn(v.z, v.w);
    }
}

// ---------------------------------------------------------------------------
// 4 weight transposes in one launch
// ---------------------------------------------------------------------------
__global__ __launch_bounds__(256)
void t512h4(const float* __restrict__ W0, const float* __restrict__ W1,
            const float* __restrict__ W2, const float* __restrict__ W3,
            __half* __restrict__ Wt)
{
    const float* W = (blockIdx.z == 0) ? W0 : (blockIdx.z == 1) ? W1 :
                     (blockIdx.z == 2) ? W2 : W3;
    __half* Wo = Wt + (size_t)blockIdx.z * EMB * EMB;
    __shared__ float t[32][33];
    int bx = blockIdx.x * 32, by = blockIdx.y * 32;
    int x = threadIdx.x & 31, y = threadIdx.x >> 5;
#pragma unroll
    for (int i = 0; i < 32; i += 8) t[y + i][x] = W[(size_t)(by + y + i) * 512 + bx + x];
    __syncthreads();
#pragma unroll
    for (int i = 0; i < 32; i += 8)
        Wo[(size_t)(bx + y + i) * 512 + by + x] = __float2half(t[x][y + i]);
}

// ---------------------------------------------------------------------------
// GEMM mainloop: 256x128 CTA tile, BK=64, 3-stage cp.async (144KB dyn smem),
// ldmatrix fragments, 8-chunk XOR swizzle, ONE barrier per stage.
// 256 threads = 8 warps (4 m x 2 n), warp tile 64x64. acc[4][8][4].
// ---------------------------------------------------------------------------
#define BM 256
#define BN 128
#define GEMM_SMEM_BYTES (3 * (BM + BN) * 64 * 2)   // 147456

__device__ __forceinline__ void gemm_mainloop(
    const __half* __restrict__ Ab, const __half* __restrict__ Bb,
    __half* As, __half* Bs, float acc[4][8][4])
{
    const int tid = threadIdx.x;
    const int wid = tid >> 5, lid = tid & 31;
    const int wm = wid & 3, wn = wid >> 2;

    const int crow = tid >> 3;       // 0..31
    const int cch  = tid & 7;        // chunk 0..7

#define ISSUE_STAGE(S, BUF)                                                               \
    do {                                                                                  \
        _Pragma("unroll")                                                                 \
        for (int i = 0; i < 8; i++) {                                                     \
            int row = crow + i * 32;                                                      \
            int sc = cch ^ (row & 7);                                                     \
            cp_async16((uint32_t)__cvta_generic_to_shared(                                \
                           As + ((size_t)(BUF) * BM + row) * 64 + sc * 8),                \
                       Ab + (size_t)row * 512 + (S) * 64 + cch * 8);                      \
        }                                                                                 \
        _Pragma("unroll")                                                                 \
        for (int i = 0; i < 4; i++) {                                                     \
            int row = crow + i * 32;                                                      \
            int sc = cch ^ (row & 7);                                                     \
            cp_async16((uint32_t)__cvta_generic_to_shared(                                \
                           Bs + ((size_t)(BUF) * BN + row) * 64 + sc * 8),                \
                       Bb + (size_t)row * 512 + (S) * 64 + cch * 8);                      \
        }                                                                                 \
        cp_commit();                                                                      \
    } while (0)

    ISSUE_STAGE(0, 0);
    ISSUE_STAGE(1, 1);

    const int lr15 = lid & 15;
    const int lhi  = lid >> 4;

    for (int s = 0; s < 8; s++) {
        const int buf = s % 3;
        if (s < 6) cp_wait<1>(); else cp_wait<0>();
        // Single barrier per stage: by the time all warps arrive, every warp
        // has consumed its stage s-1 fragments (MMA register deps), so the
        // ISSUE_STAGE below (writing buffer (s+2)%3 == (s-1)%3) cannot race.
        __syncthreads();
        if (s + 2 < 8) ISSUE_STAGE(s + 2, (s + 2) % 3);

        const __half* Abuf = As + (size_t)buf * BM * 64;
        const __half* Bbuf = Bs + (size_t)buf * BN * 64;

#pragma unroll
        for (int k16 = 0; k16 < 4; k16++) {
            const int kc = k16 * 2 + lhi;
            uint32_t a[4][4];
#pragma unroll
            for (int mt = 0; mt < 4; mt++) {
                int row = wm * 64 + mt * 16 + lr15;
                int sc = kc ^ (row & 7);
                ldm_x4(a[mt], (uint32_t)__cvta_generic_to_shared(
                                  Abuf + (size_t)row * 64 + sc * 8));
            }
            uint32_t bf[4][4];
#pragma unroll
            for (int ng = 0; ng < 4; ng++) {
                int row = wn * 64 + ng * 16 + lr15;
                int sc = kc ^ (row & 7);
                ldm_x4(bf[ng], (uint32_t)__cvta_generic_to_shared(
                                   Bbuf + (size_t)row * 64 + sc * 8));
            }
#pragma unroll
            for (int mt = 0; mt < 4; mt++)
#pragma unroll
                for (int ng = 0; ng < 4; ng++) {
                    mma_h(acc[mt][2 * ng],     a[mt], bf[ng][0], bf[ng][2]);
                    mma_h(acc[mt][2 * ng + 1], a[mt], bf[ng][1], bf[ng][3]);
                }
        }
    }
#undef ISSUE_STAGE
}

// ---------------------------------------------------------------------------
// Fused Q/K/V GEMM: grid (4, 128, 3). z=0 -> Q natural (+act),
// z=1 -> KT chunk-major (+act), z=2 -> VT chunk-major (no act).
// ---------------------------------------------------------------------------
__global__ __launch_bounds__(256, 1)
void qkv_gemm(const __half* __restrict__ Xh, const __half* __restrict__ Wth,
              const float* __restrict__ bq, const float* __restrict__ bk,
              const float* __restrict__ bv,
              __half* __restrict__ Qh, __half* __restrict__ KT, __half* __restrict__ VT)
{
    extern __shared__ __align__(16) __half smem[];
    __half* As = smem;
    __half* Bs = smem + 3 * BM * 64;

    const int z = blockIdx.z;
    const __half* Ab = Xh + (size_t)blockIdx.y * BM * 512;
    const __half* Bb = Wth + (size_t)z * EMB * EMB + (size_t)blockIdx.x * BN * 512;
    const float* bias = (z == 0) ? bq : (z == 1) ? bk : bv;

    float acc[4][8][4];
#pragma unroll
    for (int mt = 0; mt < 4; mt++)
#pragma unroll
        for (int nt = 0; nt < 8; nt++)
#pragma unroll
            for (int f = 0; f < 4; f++) acc[mt][nt][f] = 0.f;

    gemm_mainloop(Ab, Bb, As, Bs, acc);

    const int tid = threadIdx.x;
    const int wid = tid >> 5, lid = tid & 31;
    const int wm = wid & 3, wn = wid >> 2;
    const int gid = lid >> 2, tig = lid & 3;
    const int act = (z < 2);

#pragma unroll
    for (int mt = 0; mt < 4; mt++) {
        size_t r0 = (size_t)blockIdx.y * BM + wm * 64 + mt * 16 + gid;
#pragma unroll
        for (int nt = 0; nt < 8; nt++) {
            int col = blockIdx.x * BN + wn * 64 + nt * 8 + tig * 2;
            float bb0 = bias[col], bb1 = bias[col + 1];
            float v0 = acc[mt][nt][0] + bb0;
            float v1 = acc[mt][nt][1] + bb1;
            float v2 = acc[mt][nt][2] + bb0;
            float v3 = acc[mt][nt][3] + bb1;
            if (act) {
                v0 = (v0 > 0.f) ? v0 + 1.f : __expf(v0);
                v1 = (v1 > 0.f) ? v1 + 1.f : __expf(v1);
                v2 = (v2 > 0.f) ? v2 + 1.f : __expf(v2);
                v3 = (v3 > 0.f) ? v3 + 1.f : __expf(v3);
            }
            if (z == 0) {
                *reinterpret_cast<__half2*>(&Qh[r0 * 512 + col])       = __floats2half2_rn(v0, v1);
                *reinterpret_cast<__half2*>(&Qh[(r0 + 8) * 512 + col]) = __floats2half2_rn(v2, v3);
            } else {
                // chunk-major: C[bh][chunk][d][256]
                __half* C = (z == 1) ? KT : VT;
                int b = (int)(r0 >> 12), ss = (int)(r0 & 4095);
                int chunk = ss >> 8, sl = ss & 255;
                int h = col >> 6, d = col & 63;
                size_t base = ((((size_t)(b * 8 + h)) * NCHUNK + chunk) * 64 + d) * 256;
                C[base + sl]            = __float2half(v0);
                C[base + 256 + sl]      = __float2half(v1);
                C[base + sl + 8]        = __float2half(v2);
                C[base + 256 + sl + 8]  = __float2half(v3);
            }
        }
    }
}

// ---------------------------------------------------------------------------
// Output GEMM: out[M,512] = oh @ WoT^T + bo (float out)
// ---------------------------------------------------------------------------
__global__ __launch_bounds__(256, 1)
void out_gemm(const __half* __restrict__ Oh, const __half* __restrict__ Wto,
              const float* __restrict__ bias, float* __restrict__ C)
{
    extern __shared__ __align__(16) __half smem[];
    __half* As = smem;
    __half* Bs = smem + 3 * BM * 64;

    const __half* Ab = Oh + (size_t)blockIdx.y * BM * 512;
    const __half* Bb = Wto + (size_t)blockIdx.x * BN * 512;

    float acc[4][8][4];
#pragma unroll
    for (int mt = 0; mt < 4; mt++)
#pragma unroll
        for (int nt = 0; nt < 8; nt++)
#pragma unroll
            for (int f = 0; f < 4; f++) acc[mt][nt][f] = 0.f;

    gemm_mainloop(Ab, Bb, As, Bs, acc);

    const int tid = threadIdx.x;
    const int wid = tid >> 5, lid = tid & 31;
    const int wm = wid & 3, wn = wid >> 2;
    const int gid = lid >> 2, tig = lid & 3;

#pragma unroll
    for (int mt = 0; mt < 4; mt++) {
        size_t r0 = (size_t)blockIdx.y * BM + wm * 64 + mt * 16 + gid;
#pragma unroll
        for (int nt = 0; nt < 8; nt++) {
            int col = blockIdx.x * BN + wn * 64 + nt * 8 + tig * 2;
            float bb0 = bias[col], bb1 = bias[col + 1];
            *reinterpret_cast<float2*>(&C[r0 * 512 + col]) =
                make_float2(acc[mt][nt][0] + bb0, acc[mt][nt][1] + bb1);
            *reinterpret_cast<float2*>(&C[(r0 + 8) * 512 + col]) =
                make_float2(acc[mt][nt][2] + bb0, acc[mt][nt][3] + bb1);
        }
    }
}

// ---------------------------------------------------------------------------
// kv via tensor cores: per (bh, chunk of 256 s), chunk-major inputs:
//   C[d][n] = sum_s KT[d][s] * VTe[n][s], n<64 -> kv[d][m], n=64 -> ksum[d]
// ---------------------------------------------------------------------------
__global__ __launch_bounds__(128)
void kv_mma(const __half* __restrict__ KT, const __half* __restrict__ VT,
            float* __restrict__ KVP, float* __restrict__ KSP)
{
    __shared__ __align__(16) __half kt_s[64][72];
    __shared__ __align__(16) __half vt_s[72][72];

    const int tid = threadIdx.x;
    const int w = tid >> 5, lid = tid & 31;
    const int gid = lid >> 2, tig = lid & 3;
    const int bh = blockIdx.x, chunk = blockIdx.y;

    for (int i = tid; i < 8 * 72; i += 128) {
        int r = 64 + i / 72, c = i % 72;
        vt_s[r][c] = __float2half((r == 64) ? 1.f : 0.f);
    }

    const __half* ktb = KT + ((size_t)bh * NCHUNK + chunk) * 64 * 256;
    const __half* vtb = VT + ((size_t)bh * NCHUNK + chunk) * 64 * 256;

    const int crow = tid >> 1;
    const int cc   = (tid & 1) * 4;

#define KV_COPY(ST)                                                                       \
    do {                                                                                  \
        _Pragma("unroll")                                                                 \
        for (int i = 0; i < 4; i++) {                                                     \
            cp_async16((uint32_t)__cvta_generic_to_shared(&kt_s[crow][(cc + i) * 8]),     \
                       ktb + (size_t)crow * 256 + (ST) * 64 + (cc + i) * 8);              \
            cp_async16((uint32_t)__cvta_generic_to_shared(&vt_s[crow][(cc + i) * 8]),     \
                       vtb + (size_t)crow * 256 + (ST) * 64 + (cc + i) * 8);              \
        }                                                                                 \
        cp_commit();                                                                      \
    } while (0)

    float acc[9][4];
#pragma unroll
    for (int nt = 0; nt < 9; nt++)
#pragma unroll
        for (int f = 0; f < 4; f++) acc[nt][f] = 0.f;

    for (int st = 0; st < 4; st++) {
        KV_COPY(st);
        cp_wait<0>();
        __syncthreads();

        const int m0 = w * 16;
#pragma unroll
        for (int k16 = 0; k16 < 4; k16++) {
            const int k0 = k16 * 16;
            uint32_t a[4];
            a[0] = *reinterpret_cast<const uint32_t*>(&kt_s[m0 + gid    ][k0 + tig * 2]);
            a[1] = *reinterpret_cast<const uint32_t*>(&kt_s[m0 + gid + 8][k0 + tig * 2]);
            a[2] = *reinterpret_cast<const uint32_t*>(&kt_s[m0 + gid    ][k0 + 8 + tig * 2]);
            a[3] = *reinterpret_cast<const uint32_t*>(&kt_s[m0 + gid + 8][k0 + 8 + tig * 2]);
#pragma unroll
            for (int nt = 0; nt < 9; nt++) {
                uint32_t b0 = *reinterpret_cast<const uint32_t*>(&vt_s[nt * 8 + gid][k0 + tig * 2]);
                uint32_t b1 = *reinterpret_cast<const uint32_t*>(&vt_s[nt * 8 + gid][k0 + 8 + tig * 2]);
                mma_h(acc[nt], a, b0, b1);
            }
        }
        __syncthreads();
    }
#undef KV_COPY

    float* kvp = KVP + ((size_t)chunk * 64 + bh) * 4096;
    const int d0 = w * 16 + gid;
#pragma unroll
    for (int nt = 0; nt < 8; nt++) {
        int m = nt * 8 + tig * 2;
        *reinterpret_cast<float2*>(&kvp[d0 * 64 + m])       = make_float2(acc[nt][0], acc[nt][1]);
        *reinterpret_cast<float2*>(&kvp[(d0 + 8) * 64 + m]) = make_float2(acc[nt][2], acc[nt][3]);
    }
    if (tig == 0) {
        float* ksp = KSP + ((size_t)chunk * 64 + bh) * 64;
        ksp[d0]     = acc[8][0];
        ksp[d0 + 8] = acc[8][2];
    }
}

// ---------------------------------------------------------------------------
// Reduce kv partials -> half table
// ---------------------------------------------------------------------------
__global__ __launch_bounds__(256)
void kv_reduce(const float* __restrict__ KVP, const float* __restrict__ KSP,
               __half* __restrict__ KVH)
{
    const int bh = blockIdx.x, tid = threadIdx.x;
    __half* dst = KVH + (size_t)bh * 4160;
    for (int i = tid; i < 4096; i += 256) {
        float s = 0.f;
#pragma unroll
        for (int c = 0; c < NCHUNK; c++)
            s += KVP[((size_t)c * 64 + bh) * 4096 + i];
        int d = i >> 6, m = i & 63;
        dst[m * 64 + d] = __float2half(s);
    }
    if (tid < 64) {
        float s = 0.f;
#pragma unroll
        for (int c = 0; c < NCHUNK; c++)
            s += KSP[((size_t)c * 64 + bh) * 64 + tid];
        dst[4096 + tid] = __float2half(s);
    }
}

// ---------------------------------------------------------------------------
// Attention via mma: 256 tokens per CTA (2 q-tiles reuse the kv table).
// ---------------------------------------------------------------------------
__global__ __launch_bounds__(256)
void attn_mma(const __half* __restrict__ Q, const __half* __restrict__ KVH,
              __half* __restrict__ O)
{
    __shared__ __align__(16) __half kv_t[72][72];
    __shared__ __align__(16) __half q_s [128][72];

    const int tid = threadIdx.x;
    const int w   = tid >> 5;
    const int lid = tid & 31;
    const int gid = lid >> 2;
    const int tig = lid & 3;
    const int bh = blockIdx.x;
    const int b = bh >> 3, h = bh & 7;

    const uint4* kvg = reinterpret_cast<const uint4*>(KVH + (size_t)bh * 4160);
    for (int i = tid; i < 520; i += 256) {
        int m = i >> 3, dc = i & 7;
        *reinterpret_cast<uint4*>(&kv_t[m][dc * 8]) = kvg[i];
    }
    for (int i = tid; i < 7 * 72; i += 256)
        kv_t[65 + i / 72][i % 72] = __float2half(0.f);

    const int m0 = w * 16;

#pragma unroll 1
    for (int t = 0; t < 2; t++) {
        const int s0 = blockIdx.y * 256 + t * 128;

        if (t > 0) __syncthreads();
        const __half2* Q2 = reinterpret_cast<const __half2*>(
            Q + ((size_t)(b * SEQ + s0)) * EMB + h * HDIM);
        for (int i = tid; i < 128 * 32; i += 256) {
            int r = i >> 5, d2 = i & 31;
            *reinterpret_cast<__half2*>(&q_s[r][d2 * 2]) = Q2[(size_t)r * 256 + d2];
        }
        __syncthreads();

        float acc[9][4];
#pragma unroll
        for (int nt = 0; nt < 9; nt++)
#pragma unroll
            for (int f = 0; f < 4; f++) acc[nt][f] = 0.f;

#pragma unroll
        for (int k16 = 0; k16 < 4; k16++) {
            const int k0 = k16 * 16;
            uint32_t a[4];
            a[0] = *reinterpret_cast<const uint32_t*>(&q_s[m0 + gid    ][k0 + tig * 2]);
            a[1] = *reinterpret_cast<const uint32_t*>(&q_s[m0 + gid + 8][k0 + tig * 2]);
            a[2] = *reinterpret_cast<const uint32_t*>(&q_s[m0 + gid    ][k0 + 8 + tig * 2]);
            a[3] = *reinterpret_cast<const uint32_t*>(&q_s[m0 + gid + 8][k0 + 8 + tig * 2]);
#pragma unroll
            for (int nt = 0; nt < 9; nt++) {
                uint32_t b0 = *reinterpret_cast<const uint32_t*>(&kv_t[nt * 8 + gid][k0 + tig * 2]);
                uint32_t b1 = *reinterpret_cast<const uint32_t*>(&kv_t[nt * 8 + gid][k0 + 8 + tig * 2]);
                mma_h(acc[nt], a, b0, b1);
            }
        }

        float den0 = __shfl_sync(0xffffffffu, acc[8][0], lid & ~3);
        float den1 = __shfl_sync(0xffffffffu, acc[8][2], lid & ~3);
        float z0 = 1.f / (den0 + 1e-6f);
        float z1 = 1.f / (den1 + 1e-6f);

        size_t row0 = (size_t)(b * SEQ + s0 + m0 + gid);
#pragma unroll
        for (int nt = 0; nt < 8; nt++) {
            int col = h * HDIM + nt * 8 + tig * 2;
            *reinterpret_cast<__half2*>(&O[row0 * EMB + col]) =
                __floats2half2_rn(acc[nt][0] * z0, acc[nt][1] * z0);
            *reinterpret_cast<__half2*>(&O[(row0 + 8) * EMB + col]) =
                __floats2half2_rn(acc[nt][2] * z1, acc[nt][3] * z1);
        }
    }
}

// ---------------------------------------------------------------------------
extern "C" void kernel_launch(void* const* d_in, const int* in_sizes, int n_in,
                              void* d_out, int out_size)
{
    const float* x  = (const float*)d_in[0];
    const float* Wq = (const float*)d_in[1];
    const float* bq = (const float*)d_in[2];
    const float* Wk = (const float*)d_in[3];
    const float* bk = (const float*)d_in[4];
    const float* Wv = (const float*)d_in[5];
    const float* bv = (const float*)d_in[6];
    const float* Wo = (const float*)d_in[7];
    const float* bo = (const float*)d_in[8];
    float* out = (float*)d_out;

    __half *xh, *qh, *kt, *vt, *oh, *wth, *kvh;
    float *kvp, *ksp;
    cudaGetSymbolAddress((void**)&xh,  g_xh);
    cudaGetSymbolAddress((void**)&qh,  g_qh);
    cudaGetSymbolAddress((void**)&kt,  g_kt);
    cudaGetSymbolAddress((void**)&vt,  g_vt);
    cudaGetSymbolAddress((void**)&oh,  g_oh);
    cudaGetSymbolAddress((void**)&wth, g_wth);
    cudaGetSymbolAddress((void**)&kvh, g_kvh);
    cudaGetSymbolAddress((void**)&kvp, g_kvp);
    cudaGetSymbolAddress((void**)&ksp, g_ksp);

    cudaFuncSetAttribute(qkv_gemm, cudaFuncAttributeMaxDynamicSharedMemorySize, GEMM_SMEM_BYTES);
    cudaFuncSetAttribute(out_gemm, cudaFuncAttributeMaxDynamicSharedMemorySize, GEMM_SMEM_BYTES);

    int n4 = BS_ROWS * EMB / 4;
    f2h_kernel<<<n4 / 256, 256>>>(x, xh, n4);
    t512h4<<<dim3(16, 16, 4), 256>>>(Wq, Wk, Wv, Wo, wth);

    qkv_gemm<<<dim3(4, 128, 3), 256, GEMM_SMEM_BYTES>>>(xh, wth, bq, bk, bv, qh, kt, vt);

    kv_mma<<<dim3(64, NCHUNK), 128>>>(kt, vt, kvp, ksp);
    kv_reduce<<<64, 256>>>(kvp, ksp, kvh);
    attn_mma<<<dim3(64, 16), 256>>>(qh, kvh, oh);

    out_gemm<<<dim3(4, 128), 256, GEMM_SMEM_BYTES>>>(oh, wth + 3 * EMB * EMB, bo, out);
}

// round 17
// speedup vs baseline: 1.1932x; 1.1932x over previous
#include <cuda_runtime.h>
#include <cuda_fp16.h>
#include <cstdint>

// Problem constants
#define BATCH 8
#define SEQ   4096
#define EMB   512
#define NHEAD 8
#define HDIM  64
#define BS_ROWS (BATCH*SEQ)          // 32768
#define NCHUNK 16

// Scratch (device globals: allocation-free contract)
__device__ __half g_xh [BS_ROWS * EMB];
__device__ __half g_qh [BS_ROWS * EMB];
__device__ __half g_kt [BS_ROWS * EMB];            // KT[bh][chunk][d][256]
__device__ __half g_vt [BS_ROWS * EMB];            // VT[bh][chunk][m][256]
__device__ __half g_oh [BS_ROWS * EMB];
__device__ __half g_wth[4 * EMB * EMB];            // transposed half weights [N][K]
__device__ float  g_kvp[NCHUNK * 64 * HDIM * HDIM];// [chunk][bh][d][m]
__device__ float  g_ksp[NCHUNK * 64 * HDIM];       // [chunk][bh][d]
__device__ __half g_kvh[64 * (HDIM * HDIM + HDIM)];// [bh][ m*64+d ; 4096+ksum ]

// ---------------------------------------------------------------------------
// PTX helpers
// ---------------------------------------------------------------------------
__device__ __forceinline__ void mma_h(float* d, const uint32_t* a, uint32_t b0, uint32_t b1) {
    asm volatile(
        "mma.sync.aligned.m16n8k16.row.col.f32.f16.f16.f32 "
        "{%0,%1,%2,%3}, {%4,%5,%6,%7}, {%8,%9}, {%0,%1,%2,%3};"
        : "+f"(d[0]), "+f"(d[1]), "+f"(d[2]), "+f"(d[3])
        : "r"(a[0]), "r"(a[1]), "r"(a[2]), "r"(a[3]), "r"(b0), "r"(b1));
}
__device__ __forceinline__ void ldm_x4(uint32_t* r, uint32_t addr) {
    asm volatile("ldmatrix.sync.aligned.m8n8.x4.shared.b16 {%0,%1,%2,%3}, [%4];"
        : "=r"(r[0]), "=r"(r[1]), "=r"(r[2]), "=r"(r[3]) : "r"(addr));
}
__device__ __forceinline__ void cp_async16(uint32_t smem_addr, const void* gptr) {
    asm volatile("cp.async.cg.shared.global [%0], [%1], 16;" :: "r"(smem_addr), "l"(gptr));
}
__device__ __forceinline__ void cp_commit() { asm volatile("cp.async.commit_group;"); }
template <int N>
__device__ __forceinline__ void cp_wait() { asm volatile("cp.async.wait_group %0;" :: "n"(N)); }

// ---------------------------------------------------------------------------
// x -> half conversion
// ---------------------------------------------------------------------------
__global__ __launch_bounds__(256)
void f2h_kernel(const float* __restrict__ X, __half* __restrict__ Xh, int n4) {
    int i = blockIdx.x * blockDim.x + threadIdx.x;
    if (i < n4) {
        float4 v = reinterpret_cast<const float4*>(X)[i];
        reinterpret_cast<__half2*>(Xh)[i * 2]     = __floats2half2_rn(v.x, v.y);
        reinterpret_cast<__half2*>(Xh)[i * 2 + 1] = __floats2half2_rn(v.z, v.w);
    }
}

// ---------------------------------------------------------------------------
// 4 weight transposes in one launch
// ---------------------------------------------------------------------------
__global__ __launch_bounds__(256)
void t512h4(const float* __restrict__ W0, const float* __restrict__ W1,
            const float* __restrict__ W2, const float* __restrict__ W3,
            __half* __restrict__ Wt)
{
    const float* W = (blockIdx.z == 0) ? W0 : (blockIdx.z == 1) ? W1 :
                     (blockIdx.z == 2) ? W2 : W3;
    __half* Wo = Wt + (size_t)blockIdx.z * EMB * EMB;
    __shared__ float t[32][33];
    int bx = blockIdx.x * 32, by = blockIdx.y * 32;
    int x = threadIdx.x & 31, y = threadIdx.x >> 5;
#pragma unroll
    for (int i = 0; i < 32; i += 8) t[y + i][x] = W[(size_t)(by + y + i) * 512 + bx + x];
    __syncthreads();
#pragma unroll
    for (int i = 0; i < 32; i += 8)
        Wo[(size_t)(bx + y + i) * 512 + by + x] = __float2half(t[x][y + i]);
}

// ---------------------------------------------------------------------------
// GEMM mainloop: 128x128 tile, BK=64, 3-stage cp.async (96KB dynamic smem),
// ldmatrix fragments, 8-chunk XOR swizzle, ONE barrier per stage.
// 256 threads = 8 warps (4 m x 2 n), warp tile 32x64. acc[2][8][4].
// (Reverted to the proven R11 configuration: 2 CTAs/SM.)
// ---------------------------------------------------------------------------
#define GEMM_SMEM_BYTES (2 * 3 * 128 * 64 * 2)   // A + B, 3 stages: 98304

__device__ __forceinline__ void gemm_mainloop(
    const __half* __restrict__ Ab, const __half* __restrict__ Bb,
    __half* As, __half* Bs, float acc[2][8][4])
{
    const int tid = threadIdx.x;
    const int wid = tid >> 5, lid = tid & 31;
    const int wm = wid & 3, wn = wid >> 2;

    const int crow = tid >> 3;       // 0..31
    const int cch  = tid & 7;        // chunk 0..7

#define ISSUE_STAGE(S, BUF)                                                               \
    do {                                                                                  \
        _Pragma("unroll")                                                                 \
        for (int i = 0; i < 4; i++) {                                                     \
            int row = crow + i * 32;                                                      \
            int sc = cch ^ (row & 7);                                                     \
            cp_async16((uint32_t)__cvta_generic_to_shared(                                \
                           As + ((size_t)(BUF) * 128 + row) * 64 + sc * 8),               \
                       Ab + (size_t)row * 512 + (S) * 64 + cch * 8);                      \
            cp_async16((uint32_t)__cvta_generic_to_shared(                                \
                           Bs + ((size_t)(BUF) * 128 + row) * 64 + sc * 8),               \
                       Bb + (size_t)row * 512 + (S) * 64 + cch * 8);                      \
        }                                                                                 \
        cp_commit();                                                                      \
    } while (0)

    ISSUE_STAGE(0, 0);
    ISSUE_STAGE(1, 1);

    const int lr15 = lid & 15;
    const int lhi  = lid >> 4;

    for (int s = 0; s < 8; s++) {
        const int buf = s % 3;
        if (s < 6) cp_wait<1>(); else cp_wait<0>();
        // Single barrier per stage: by the time all warps arrive here, every
        // warp has consumed its stage s-1 fragments (MMA register deps), so
        // the ISSUE_STAGE below (writing buffer (s+2)%3 == (s-1)%3) cannot race.
        __syncthreads();
        if (s + 2 < 8) ISSUE_STAGE(s + 2, (s + 2) % 3);

        const __half* Abuf = As + (size_t)buf * 128 * 64;
        const __half* Bbuf = Bs + (size_t)buf * 128 * 64;

#pragma unroll
        for (int k16 = 0; k16 < 4; k16++) {
            const int kc = k16 * 2 + lhi;
            uint32_t a[2][4];
#pragma unroll
            for (int mt = 0; mt < 2; mt++) {
                int row = wm * 32 + mt * 16 + lr15;
                int sc = kc ^ (row & 7);
                ldm_x4(a[mt], (uint32_t)__cvta_generic_to_shared(
                                  Abuf + (size_t)row * 64 + sc * 8));
            }
            uint32_t bf[4][4];
#pragma unroll
            for (int ng = 0; ng < 4; ng++) {
                int row = wn * 64 + ng * 16 + lr15;
                int sc = kc ^ (row & 7);
                ldm_x4(bf[ng], (uint32_t)__cvta_generic_to_shared(
                                   Bbuf + (size_t)row * 64 + sc * 8));
            }
#pragma unroll
            for (int mt = 0; mt < 2; mt++)
#pragma unroll
                for (int ng = 0; ng < 4; ng++) {
                    mma_h(acc[mt][2 * ng],     a[mt], bf[ng][0], bf[ng][2]);
                    mma_h(acc[mt][2 * ng + 1], a[mt], bf[ng][1], bf[ng][3]);
                }
        }
    }
#undef ISSUE_STAGE
}

// ---------------------------------------------------------------------------
// Fused Q/K/V GEMM: grid (4, 256, 3). z=0 -> Q natural (+act),
// z=1 -> KT chunk-major (+act), z=2 -> VT chunk-major (no act).
// ---------------------------------------------------------------------------
__global__ __launch_bounds__(256, 2)
void qkv_gemm(const __half* __restrict__ Xh, const __half* __restrict__ Wth,
              const float* __restrict__ bq, const float* __restrict__ bk,
              const float* __restrict__ bv,
              __half* __restrict__ Qh, __half* __restrict__ KT, __half* __restrict__ VT)
{
    extern __shared__ __align__(16) __half smem[];
    __half* As = smem;
    __half* Bs = smem + 3 * 128 * 64;

    const int z = blockIdx.z;
    const __half* Ab = Xh + (size_t)blockIdx.y * 128 * 512;
    const __half* Bb = Wth + (size_t)z * EMB * EMB + (size_t)blockIdx.x * 128 * 512;
    const float* bias = (z == 0) ? bq : (z == 1) ? bk : bv;

    float acc[2][8][4];
#pragma unroll
    for (int mt = 0; mt < 2; mt++)
#pragma unroll
        for (int nt = 0; nt < 8; nt++)
#pragma unroll
            for (int f = 0; f < 4; f++) acc[mt][nt][f] = 0.f;

    gemm_mainloop(Ab, Bb, As, Bs, acc);

    const int tid = threadIdx.x;
    const int wid = tid >> 5, lid = tid & 31;
    const int wm = wid & 3, wn = wid >> 2;
    const int gid = lid >> 2, tig = lid & 3;
    const int act = (z < 2);

#pragma unroll
    for (int mt = 0; mt < 2; mt++) {
        size_t r0 = (size_t)blockIdx.y * 128 + wm * 32 + mt * 16 + gid;
#pragma unroll
        for (int nt = 0; nt < 8; nt++) {
            int col = blockIdx.x * 128 + wn * 64 + nt * 8 + tig * 2;
            float bb0 = bias[col], bb1 = bias[col + 1];
            float v0 = acc[mt][nt][0] + bb0;
            float v1 = acc[mt][nt][1] + bb1;
            float v2 = acc[mt][nt][2] + bb0;
            float v3 = acc[mt][nt][3] + bb1;
            if (act) {
                v0 = (v0 > 0.f) ? v0 + 1.f : __expf(v0);
                v1 = (v1 > 0.f) ? v1 + 1.f : __expf(v1);
                v2 = (v2 > 0.f) ? v2 + 1.f : __expf(v2);
                v3 = (v3 > 0.f) ? v3 + 1.f : __expf(v3);
            }
            if (z == 0) {
                *reinterpret_cast<__half2*>(&Qh[r0 * 512 + col])       = __floats2half2_rn(v0, v1);
                *reinterpret_cast<__half2*>(&Qh[(r0 + 8) * 512 + col]) = __floats2half2_rn(v2, v3);
            } else {
                // chunk-major: C[bh][chunk][d][256]
                __half* C = (z == 1) ? KT : VT;
                int b = (int)(r0 >> 12), ss = (int)(r0 & 4095);
                int chunk = ss >> 8, sl = ss & 255;
                int h = col >> 6, d = col & 63;
                size_t base = ((((size_t)(b * 8 + h)) * NCHUNK + chunk) * 64 + d) * 256;
                C[base + sl]            = __float2half(v0);
                C[base + 256 + sl]      = __float2half(v1);
                C[base + sl + 8]        = __float2half(v2);
                C[base + 256 + sl + 8]  = __float2half(v3);
            }
        }
    }
}

// ---------------------------------------------------------------------------
// Output GEMM: out[M,512] = oh @ WoT^T + bo (float out)
// ---------------------------------------------------------------------------
__global__ __launch_bounds__(256, 2)
void out_gemm(const __half* __restrict__ Oh, const __half* __restrict__ Wto,
              const float* __restrict__ bias, float* __restrict__ C)
{
    extern __shared__ __align__(16) __half smem[];
    __half* As = smem;
    __half* Bs = smem + 3 * 128 * 64;

    const __half* Ab = Oh + (size_t)blockIdx.y * 128 * 512;
    const __half* Bb = Wto + (size_t)blockIdx.x * 128 * 512;

    float acc[2][8][4];
#pragma unroll
    for (int mt = 0; mt < 2; mt++)
#pragma unroll
        for (int nt = 0; nt < 8; nt++)
#pragma unroll
            for (int f = 0; f < 4; f++) acc[mt][nt][f] = 0.f;

    gemm_mainloop(Ab, Bb, As, Bs, acc);

    const int tid = threadIdx.x;
    const int wid = tid >> 5, lid = tid & 31;
    const int wm = wid & 3, wn = wid >> 2;
    const int gid = lid >> 2, tig = lid & 3;

#pragma unroll
    for (int mt = 0; mt < 2; mt++) {
        size_t r0 = (size_t)blockIdx.y * 128 + wm * 32 + mt * 16 + gid;
#pragma unroll
        for (int nt = 0; nt < 8; nt++) {
            int col = blockIdx.x * 128 + wn * 64 + nt * 8 + tig * 2;
            float bb0 = bias[col], bb1 = bias[col + 1];
            *reinterpret_cast<float2*>(&C[r0 * 512 + col]) =
                make_float2(acc[mt][nt][0] + bb0, acc[mt][nt][1] + bb1);
            *reinterpret_cast<float2*>(&C[(r0 + 8) * 512 + col]) =
                make_float2(acc[mt][nt][2] + bb0, acc[mt][nt][3] + bb1);
        }
    }
}

// ---------------------------------------------------------------------------
// kv via tensor cores: per (bh, chunk of 256 s), chunk-major inputs:
//   C[d][n] = sum_s KT[d][s] * VTe[n][s], n<64 -> kv[d][m], n=64 -> ksum[d]
// Single-buffered smem (20KB), contiguous 64KB per-CTA input block.
// ---------------------------------------------------------------------------
__global__ __launch_bounds__(128)
void kv_mma(const __half* __restrict__ KT, const __half* __restrict__ VT,
            float* __restrict__ KVP, float* __restrict__ KSP)
{
    __shared__ __align__(16) __half kt_s[64][72];
    __shared__ __align__(16) __half vt_s[72][72];

    const int tid = threadIdx.x;
    const int w = tid >> 5, lid = tid & 31;
    const int gid = lid >> 2, tig = lid & 3;
    const int bh = blockIdx.x, chunk = blockIdx.y;

    for (int i = tid; i < 8 * 72; i += 128) {
        int r = 64 + i / 72, c = i % 72;
        vt_s[r][c] = __float2half((r == 64) ? 1.f : 0.f);
    }

    const __half* ktb = KT + ((size_t)bh * NCHUNK + chunk) * 64 * 256;
    const __half* vtb = VT + ((size_t)bh * NCHUNK + chunk) * 64 * 256;

    const int crow = tid >> 1;
    const int cc   = (tid & 1) * 4;

#define KV_COPY(ST)                                                                       \
    do {                                                                                  \
        _Pragma("unroll")                                                                 \
        for (int i = 0; i < 4; i++) {                                                     \
            cp_async16((uint32_t)__cvta_generic_to_shared(&kt_s[crow][(cc + i) * 8]),     \
                       ktb + (size_t)crow * 256 + (ST) * 64 + (cc + i) * 8);              \
            cp_async16((uint32_t)__cvta_generic_to_shared(&vt_s[crow][(cc + i) * 8]),     \
                       vtb + (size_t)crow * 256 + (ST) * 64 + (cc + i) * 8);              \
        }                                                                                 \
        cp_commit();                                                                      \
    } while (0)

    float acc[9][4];
#pragma unroll
    for (int nt = 0; nt < 9; nt++)
#pragma unroll
        for (int f = 0; f < 4; f++) acc[nt][f] = 0.f;

    for (int st = 0; st < 4; st++) {
        KV_COPY(st);
        cp_wait<0>();
        __syncthreads();

        const int m0 = w * 16;
#pragma unroll
        for (int k16 = 0; k16 < 4; k16++) {
            const int k0 = k16 * 16;
            uint32_t a[4];
            a[0] = *reinterpret_cast<const uint32_t*>(&kt_s[m0 + gid    ][k0 + tig * 2]);
            a[1] = *reinterpret_cast<const uint32_t*>(&kt_s[m0 + gid + 8][k0 + tig * 2]);
            a[2] = *reinterpret_cast<const uint32_t*>(&kt_s[m0 + gid    ][k0 + 8 + tig * 2]);
            a[3] = *reinterpret_cast<const uint32_t*>(&kt_s[m0 + gid + 8][k0 + 8 + tig * 2]);
#pragma unroll
            for (int nt = 0; nt < 9; nt++) {
                uint32_t b0 = *reinterpret_cast<const uint32_t*>(&vt_s[nt * 8 + gid][k0 + tig * 2]);
                uint32_t b1 = *reinterpret_cast<const uint32_t*>(&vt_s[nt * 8 + gid][k0 + 8 + tig * 2]);
                mma_h(acc[nt], a, b0, b1);
            }
        }
        __syncthreads();
    }
#undef KV_COPY

    float* kvp = KVP + ((size_t)chunk * 64 + bh) * 4096;
    const int d0 = w * 16 + gid;
#pragma unroll
    for (int nt = 0; nt < 8; nt++) {
        int m = nt * 8 + tig * 2;
        *reinterpret_cast<float2*>(&kvp[d0 * 64 + m])       = make_float2(acc[nt][0], acc[nt][1]);
        *reinterpret_cast<float2*>(&kvp[(d0 + 8) * 64 + m]) = make_float2(acc[nt][2], acc[nt][3]);
    }
    if (tig == 0) {
        float* ksp = KSP + ((size_t)chunk * 64 + bh) * 64;
        ksp[d0]     = acc[8][0];
        ksp[d0 + 8] = acc[8][2];
    }
}

// ---------------------------------------------------------------------------
// Reduce kv partials -> half table
// ---------------------------------------------------------------------------
__global__ __launch_bounds__(256)
void kv_reduce(const float* __restrict__ KVP, const float* __restrict__ KSP,
               __half* __restrict__ KVH)
{
    const int bh = blockIdx.x, tid = threadIdx.x;
    __half* dst = KVH + (size_t)bh * 4160;
    for (int i = tid; i < 4096; i += 256) {
        float s = 0.f;
#pragma unroll
        for (int c = 0; c < NCHUNK; c++)
            s += KVP[((size_t)c * 64 + bh) * 4096 + i];
        int d = i >> 6, m = i & 63;
        dst[m * 64 + d] = __float2half(s);
    }
    if (tid < 64) {
        float s = 0.f;
#pragma unroll
        for (int c = 0; c < NCHUNK; c++)
            s += KSP[((size_t)c * 64 + bh) * 64 + tid];
        dst[4096 + tid] = __float2half(s);
    }
}

// ---------------------------------------------------------------------------
// Attention via mma: 256 tokens per CTA (2 q-tiles reuse the kv table).
// ---------------------------------------------------------------------------
__global__ __launch_bounds__(256)
void attn_mma(const __half* __restrict__ Q, const __half* __restrict__ KVH,
              __half* __restrict__ O)
{
    __shared__ __align__(16) __half kv_t[72][72];
    __shared__ __align__(16) __half q_s [128][72];

    const int tid = threadIdx.x;
    const int w   = tid >> 5;
    const int lid = tid & 31;
    const int gid = lid >> 2;
    const int tig = lid & 3;
    const int bh = blockIdx.x;
    const int b = bh >> 3, h = bh & 7;

    const uint4* kvg = reinterpret_cast<const uint4*>(KVH + (size_t)bh * 4160);
    for (int i = tid; i < 520; i += 256) {
        int m = i >> 3, dc = i & 7;
        *reinterpret_cast<uint4*>(&kv_t[m][dc * 8]) = kvg[i];
    }
    for (int i = tid; i < 7 * 72; i += 256)
        kv_t[65 + i / 72][i % 72] = __float2half(0.f);

    const int m0 = w * 16;

#pragma unroll 1
    for (int t = 0; t < 2; t++) {
        const int s0 = blockIdx.y * 256 + t * 128;

        if (t > 0) __syncthreads();
        const __half2* Q2 = reinterpret_cast<const __half2*>(
            Q + ((size_t)(b * SEQ + s0)) * EMB + h * HDIM);
        for (int i = tid; i < 128 * 32; i += 256) {
            int r = i >> 5, d2 = i & 31;
            *reinterpret_cast<__half2*>(&q_s[r][d2 * 2]) = Q2[(size_t)r * 256 + d2];
        }
        __syncthreads();

        float acc[9][4];
#pragma unroll
        for (int nt = 0; nt < 9; nt++)
#pragma unroll
            for (int f = 0; f < 4; f++) acc[nt][f] = 0.f;

#pragma unroll
        for (int k16 = 0; k16 < 4; k16++) {
            const int k0 = k16 * 16;
            uint32_t a[4];
            a[0] = *reinterpret_cast<const uint32_t*>(&q_s[m0 + gid    ][k0 + tig * 2]);
            a[1] = *reinterpret_cast<const uint32_t*>(&q_s[m0 + gid + 8][k0 + tig * 2]);
            a[2] = *reinterpret_cast<const uint32_t*>(&q_s[m0 + gid    ][k0 + 8 + tig * 2]);
            a[3] = *reinterpret_cast<const uint32_t*>(&q_s[m0 + gid + 8][k0 + 8 + tig * 2]);
#pragma unroll
            for (int nt = 0; nt < 9; nt++) {
                uint32_t b0 = *reinterpret_cast<const uint32_t*>(&kv_t[nt * 8 + gid][k0 + tig * 2]);
                uint32_t b1 = *reinterpret_cast<const uint32_t*>(&kv_t[nt * 8 + gid][k0 + 8 + tig * 2]);
                mma_h(acc[nt], a, b0, b1);
            }
        }

        float den0 = __shfl_sync(0xffffffffu, acc[8][0], lid & ~3);
        float den1 = __shfl_sync(0xffffffffu, acc[8][2], lid & ~3);
        float z0 = 1.f / (den0 + 1e-6f);
        float z1 = 1.f / (den1 + 1e-6f);

        size_t row0 = (size_t)(b * SEQ + s0 + m0 + gid);
#pragma unroll
        for (int nt = 0; nt < 8; nt++) {
            int col = h * HDIM + nt * 8 + tig * 2;
            *reinterpret_cast<__half2*>(&O[row0 * EMB + col]) =
                __floats2half2_rn(acc[nt][0] * z0, acc[nt][1] * z0);
            *reinterpret_cast<__half2*>(&O[(row0 + 8) * EMB + col]) =
                __floats2half2_rn(acc[nt][2] * z1, acc[nt][3] * z1);
        }
    }
}

// ---------------------------------------------------------------------------
extern "C" void kernel_launch(void* const* d_in, const int* in_sizes, int n_in,
                              void* d_out, int out_size)
{
    const float* x  = (const float*)d_in[0];
    const float* Wq = (const float*)d_in[1];
    const float* bq = (const float*)d_in[2];
    const float* Wk = (const float*)d_in[3];
    const float* bk = (const float*)d_in[4];
    const float* Wv = (const float*)d_in[5];
    const float* bv = (const float*)d_in[6];
    const float* Wo = (const float*)d_in[7];
    const float* bo = (const float*)d_in[8];
    float* out = (float*)d_out;

    __half *xh, *qh, *kt, *vt, *oh, *wth, *kvh;
    float *kvp, *ksp;
    cudaGetSymbolAddress((void**)&xh,  g_xh);
    cudaGetSymbolAddress((void**)&qh,  g_qh);
    cudaGetSymbolAddress((void**)&kt,  g_kt);
    cudaGetSymbolAddress((void**)&vt,  g_vt);
    cudaGetSymbolAddress((void**)&oh,  g_oh);
    cudaGetSymbolAddress((void**)&wth, g_wth);
    cudaGetSymbolAddress((void**)&kvh, g_kvh);
    cudaGetSymbolAddress((void**)&kvp, g_kvp);
    cudaGetSymbolAddress((void**)&ksp, g_ksp);

    cudaFuncSetAttribute(qkv_gemm, cudaFuncAttributeMaxDynamicSharedMemorySize, GEMM_SMEM_BYTES);
    cudaFuncSetAttribute(out_gemm, cudaFuncAttributeMaxDynamicSharedMemorySize, GEMM_SMEM_BYTES);

    int n4 = BS_ROWS * EMB / 4;
    f2h_kernel<<<n4 / 256, 256>>>(x, xh, n4);
    t512h4<<<dim3(16, 16, 4), 256>>>(Wq, Wk, Wv, Wo, wth);

    qkv_gemm<<<dim3(4, 256, 3), 256, GEMM_SMEM_BYTES>>>(xh, wth, bq, bk, bv, qh, kt, vt);

    kv_mma<<<dim3(64, NCHUNK), 128>>>(kt, vt, kvp, ksp);
    kv_reduce<<<64, 256>>>(kvp, ksp, kvh);
    attn_mma<<<dim3(64, 16), 256>>>(qh, kvh, oh);

    out_gemm<<<dim3(4, 256), 256, GEMM_SMEM_BYTES>>>(oh, wth + 3 * EMB * EMB, bo, out);
}